// round 1
// baseline (speedup 1.0000x reference)
#include <cuda_runtime.h>
#include <math.h>

// Problem constants (fixed by the reference)
#define B_ROWS 16
#define D_LEN  2097152              // floats per row
#define D4     (D_LEN / 4)          // 524288 float4 per row
#define TPB    256
#define BPR    128                  // blocks per row
#define ITERS  (D4 / (TPB * BPR))   // 16 float4 per thread

// Scratch: per-row sum of squared diffs (no cudaMalloc allowed)
__device__ float g_rowsum[B_ROWS];

__global__ void zero_kernel() {
    if (threadIdx.x < B_ROWS) g_rowsum[threadIdx.x] = 0.0f;
}

__global__ __launch_bounds__(TPB) void reduce_kernel(
    const float* __restrict__ outp, const float* __restrict__ labp)
{
    const int row = blockIdx.y;
    const float4* __restrict__ o = (const float4*)(outp + (size_t)row * D_LEN);
    const float4* __restrict__ l = (const float4*)(labp + (size_t)row * D_LEN);

    const int base   = blockIdx.x * TPB + threadIdx.x;  // float4 index
    const int stride = BPR * TPB;                       // 32768

    float s = 0.0f;
#pragma unroll
    for (int i = 0; i < ITERS; ++i) {
        const int idx = base + i * stride;
        float4 a = o[idx];
        float4 b = l[idx];
        float dx = a.x - b.x;
        float dy = a.y - b.y;
        float dz = a.z - b.z;
        float dw = a.w - b.w;
        s = fmaf(dx, dx, s);
        s = fmaf(dy, dy, s);
        s = fmaf(dz, dz, s);
        s = fmaf(dw, dw, s);
    }

    // warp reduce
#pragma unroll
    for (int off = 16; off > 0; off >>= 1)
        s += __shfl_down_sync(0xffffffffu, s, off);

    __shared__ float sm[TPB / 32];
    if ((threadIdx.x & 31) == 0) sm[threadIdx.x >> 5] = s;
    __syncthreads();

    if (threadIdx.x < 32) {
        float v = (threadIdx.x < TPB / 32) ? sm[threadIdx.x] : 0.0f;
#pragma unroll
        for (int off = 16; off > 0; off >>= 1)
            v += __shfl_down_sync(0xffffffffu, v, off);
        if (threadIdx.x == 0) atomicAdd(&g_rowsum[row], v);
    }
}

__global__ void finalize_kernel(float* __restrict__ dst) {
    float v = (threadIdx.x < B_ROWS) ? sqrtf(g_rowsum[threadIdx.x]) : 0.0f;
#pragma unroll
    for (int off = 16; off > 0; off >>= 1)
        v += __shfl_down_sync(0xffffffffu, v, off);
    if (threadIdx.x == 0) dst[0] = v * (1.0f / (float)B_ROWS);
}

extern "C" void kernel_launch(void* const* d_in, const int* in_sizes, int n_in,
                              void* d_out, int out_size)
{
    const float* outp = (const float*)d_in[0];
    const float* labp = (const float*)d_in[1];
    float* dst = (float*)d_out;

    zero_kernel<<<1, 32>>>();
    dim3 grid(BPR, B_ROWS);
    reduce_kernel<<<grid, TPB>>>(outp, labp);
    finalize_kernel<<<1, 32>>>(dst);
}

// round 2
// speedup vs baseline: 1.0409x; 1.0409x over previous
#include <cuda_runtime.h>
#include <math.h>

// Problem constants (fixed by the reference)
#define B_ROWS 16
#define D_LEN  2097152              // floats per row
#define D4     (D_LEN / 4)          // 524288 float4 per row
#define TPB    256
#define BPR    128                  // blocks per row
#define NBLK   (BPR * B_ROWS)       // 2048 total blocks
#define ITERS  (D4 / (TPB * BPR))   // 16 float4 per thread

// Scratch (zero-initialized at module load; last block resets after use so
// every graph replay starts from the same state — deterministic).
__device__ float        g_rowsum[B_ROWS];
__device__ unsigned int g_arrived;

__global__ __launch_bounds__(TPB) void euclid_loss_kernel(
    const float* __restrict__ outp, const float* __restrict__ labp,
    float* __restrict__ dst)
{
    const int row = blockIdx.y;
    const float4* __restrict__ o = (const float4*)(outp + (size_t)row * D_LEN);
    const float4* __restrict__ l = (const float4*)(labp + (size_t)row * D_LEN);

    const int base   = blockIdx.x * TPB + threadIdx.x;  // float4 index
    const int stride = BPR * TPB;                       // 32768

    float s = 0.0f;
#pragma unroll
    for (int i = 0; i < ITERS; ++i) {
        const int idx = base + i * stride;
        float4 a = __ldcs(&o[idx]);   // streaming: no reuse, evict-first
        float4 b = __ldcs(&l[idx]);
        float dx = a.x - b.x;
        float dy = a.y - b.y;
        float dz = a.z - b.z;
        float dw = a.w - b.w;
        s = fmaf(dx, dx, s);
        s = fmaf(dy, dy, s);
        s = fmaf(dz, dz, s);
        s = fmaf(dw, dw, s);
    }

    // warp reduce
#pragma unroll
    for (int off = 16; off > 0; off >>= 1)
        s += __shfl_down_sync(0xffffffffu, s, off);

    __shared__ float sm[TPB / 32];
    __shared__ bool  last;
    if ((threadIdx.x & 31) == 0) sm[threadIdx.x >> 5] = s;
    __syncthreads();

    if (threadIdx.x < 32) {
        float v = (threadIdx.x < TPB / 32) ? sm[threadIdx.x] : 0.0f;
#pragma unroll
        for (int off = 16; off > 0; off >>= 1)
            v += __shfl_down_sync(0xffffffffu, v, off);
        if (threadIdx.x == 0) {
            atomicAdd(&g_rowsum[row], v);
            __threadfence();  // make row partial globally visible before arrival
            unsigned int prev = atomicAdd(&g_arrived, 1u);
            last = (prev == (unsigned int)(NBLK - 1));
        }
    }
    __syncthreads();

    // Final block: all partials are in g_rowsum (fence+atomic handshake).
    if (last) {
        __threadfence();  // acquire side: see all other blocks' g_rowsum adds
        if (threadIdx.x < 32) {
            float v = (threadIdx.x < B_ROWS) ? sqrtf(g_rowsum[threadIdx.x]) : 0.0f;
#pragma unroll
            for (int off = 16; off > 0; off >>= 1)
                v += __shfl_down_sync(0xffffffffu, v, off);
            if (threadIdx.x == 0) dst[0] = v * (1.0f / (float)B_ROWS);
            // Reset scratch for the next graph replay.
            if (threadIdx.x < B_ROWS) g_rowsum[threadIdx.x] = 0.0f;
            if (threadIdx.x == 0)     g_arrived = 0u;
        }
    }
}

extern "C" void kernel_launch(void* const* d_in, const int* in_sizes, int n_in,
                              void* d_out, int out_size)
{
    const float* outp = (const float*)d_in[0];
    const float* labp = (const float*)d_in[1];
    float* dst = (float*)d_out;

    dim3 grid(BPR, B_ROWS);
    euclid_loss_kernel<<<grid, TPB>>>(outp, labp, dst);
}

// round 3
// speedup vs baseline: 1.0478x; 1.0066x over previous
#include <cuda_runtime.h>
#include <math.h>

// Problem constants (fixed by the reference)
#define B_ROWS 16
#define D_LEN  2097152              // floats per row
#define D4     (D_LEN / 4)          // 524288 float4 per row
#define TPB    256
#define BPR    128                  // blocks per row
#define NBLK   (BPR * B_ROWS)       // 2048 total blocks
#define ITERS  (D4 / (TPB * BPR))   // 16 float4 per thread
#define BATCH  4                    // float4 loads in flight per operand
#define OUTER  (ITERS / BATCH)      // 4

// Scratch (zero-initialized at module load; last block resets after use so
// every graph replay starts from the same state — deterministic).
__device__ float        g_rowsum[B_ROWS];
__device__ unsigned int g_arrived;

__global__ __launch_bounds__(TPB, 4) void euclid_loss_kernel(
    const float* __restrict__ outp, const float* __restrict__ labp,
    float* __restrict__ dst)
{
    const int row = blockIdx.y;
    const float4* __restrict__ o = (const float4*)(outp + (size_t)row * D_LEN);
    const float4* __restrict__ l = (const float4*)(labp + (size_t)row * D_LEN);

    const int base   = blockIdx.x * TPB + threadIdx.x;  // float4 index
    const int stride = BPR * TPB;                       // 32768 float4

    float s0 = 0.0f, s1 = 0.0f, s2 = 0.0f, s3 = 0.0f;

#pragma unroll
    for (int i = 0; i < OUTER; ++i) {
        // Issue all 8 LDG.128 back-to-back (front-batched -> high MLP)
        float4 a0, a1, a2, a3, b0, b1, b2, b3;
        const int j0 = base + (i * BATCH + 0) * stride;
        const int j1 = base + (i * BATCH + 1) * stride;
        const int j2 = base + (i * BATCH + 2) * stride;
        const int j3 = base + (i * BATCH + 3) * stride;
        a0 = __ldcs(&o[j0]); a1 = __ldcs(&o[j1]);
        a2 = __ldcs(&o[j2]); a3 = __ldcs(&o[j3]);
        b0 = __ldcs(&l[j0]); b1 = __ldcs(&l[j1]);
        b2 = __ldcs(&l[j2]); b3 = __ldcs(&l[j3]);

        float dx, dy, dz, dw;
        dx = a0.x - b0.x; dy = a0.y - b0.y; dz = a0.z - b0.z; dw = a0.w - b0.w;
        s0 = fmaf(dx, dx, s0); s1 = fmaf(dy, dy, s1);
        s2 = fmaf(dz, dz, s2); s3 = fmaf(dw, dw, s3);

        dx = a1.x - b1.x; dy = a1.y - b1.y; dz = a1.z - b1.z; dw = a1.w - b1.w;
        s0 = fmaf(dx, dx, s0); s1 = fmaf(dy, dy, s1);
        s2 = fmaf(dz, dz, s2); s3 = fmaf(dw, dw, s3);

        dx = a2.x - b2.x; dy = a2.y - b2.y; dz = a2.z - b2.z; dw = a2.w - b2.w;
        s0 = fmaf(dx, dx, s0); s1 = fmaf(dy, dy, s1);
        s2 = fmaf(dz, dz, s2); s3 = fmaf(dw, dw, s3);

        dx = a3.x - b3.x; dy = a3.y - b3.y; dz = a3.z - b3.z; dw = a3.w - b3.w;
        s0 = fmaf(dx, dx, s0); s1 = fmaf(dy, dy, s1);
        s2 = fmaf(dz, dz, s2); s3 = fmaf(dw, dw, s3);
    }

    float s = (s0 + s1) + (s2 + s3);

    // warp reduce
#pragma unroll
    for (int off = 16; off > 0; off >>= 1)
        s += __shfl_down_sync(0xffffffffu, s, off);

    __shared__ float sm[TPB / 32];
    __shared__ bool  last;
    if ((threadIdx.x & 31) == 0) sm[threadIdx.x >> 5] = s;
    __syncthreads();

    if (threadIdx.x < 32) {
        float v = (threadIdx.x < TPB / 32) ? sm[threadIdx.x] : 0.0f;
#pragma unroll
        for (int off = 16; off > 0; off >>= 1)
            v += __shfl_down_sync(0xffffffffu, v, off);
        if (threadIdx.x == 0) {
            atomicAdd(&g_rowsum[row], v);
            __threadfence();  // make row partial globally visible before arrival
            unsigned int prev = atomicAdd(&g_arrived, 1u);
            last = (prev == (unsigned int)(NBLK - 1));
        }
    }
    __syncthreads();

    // Final block: all partials are in g_rowsum (fence+atomic handshake).
    if (last) {
        __threadfence();  // acquire: see all other blocks' g_rowsum adds
        if (threadIdx.x < 32) {
            float v = (threadIdx.x < B_ROWS) ? sqrtf(g_rowsum[threadIdx.x]) : 0.0f;
#pragma unroll
            for (int off = 16; off > 0; off >>= 1)
                v += __shfl_down_sync(0xffffffffu, v, off);
            if (threadIdx.x == 0) dst[0] = v * (1.0f / (float)B_ROWS);
            // Reset scratch for the next graph replay.
            if (threadIdx.x < B_ROWS) g_rowsum[threadIdx.x] = 0.0f;
            if (threadIdx.x == 0)     g_arrived = 0u;
        }
    }
}

extern "C" void kernel_launch(void* const* d_in, const int* in_sizes, int n_in,
                              void* d_out, int out_size)
{
    const float* outp = (const float*)d_in[0];
    const float* labp = (const float*)d_in[1];
    float* dst = (float*)d_out;

    dim3 grid(BPR, B_ROWS);
    euclid_loss_kernel<<<grid, TPB>>>(outp, labp, dst);
}